// round 9
// baseline (speedup 1.0000x reference)
#include <cuda_runtime.h>
#include <math.h>

#define SB 8
#define CH 32
#define KM 32
#define OC 32
#define SS 2048
#define DF (1.0f/2047.0f)
#define NB 128

// ---- scratch (device globals: allocation-free rule) ----
__device__ __align__(16) float g_xsum[SB*SS];            // [b][s]
__device__ float g_cpart[NB*CH];                         // per-block per-channel partials
__device__ __align__(16) float g_P[(size_t)SB*SS*KM];    // [b][t][k] fwd decay scan
__device__ __align__(16) float g_Q[(size_t)SB*SS*KM];    // [b][t][k] bwd decay scan
__device__ __align__(16) float g_wsum[KM*OC];            // [k][o]
__device__ float g_a[KM], g_poles[KM];
__device__ float g_D;
__device__ unsigned g_bar0, g_bar1;                      // monotonic barrier counters

struct P1 { float4 sacc[32][32]; float4 sacc2[4][32]; float sws[16][32]; };
struct P2 { float4 xs4[512]; float lc[32*33]; float sxm[32][9]; float a[KM]; float aG[KM]; };
struct P3 { float ws[KM*OC]; float zt[2][32*32]; float st[2][32*33];
            float pol[KM]; float aa[KM]; int smL[2][32]; int smR[2][32]; };
union __align__(16) SMem { P1 p1; P2 p2; P3 p3; };

// replicate reference float32 coords: linspace(0,1,2048)
__device__ __forceinline__ float coordf(int i) {
    return (i == SS - 1) ? 1.0f : ((float)i) * DF;
}

// Wrap-free monotonic grid barrier. Counter only ever advances by NB per
// launch, so (old & ~(NB-1)) + NB is this cohort's release value — correct
// across graph replays and ncu kernel-replay (with or without memory restore).
// Spin uses an L2 atomic read (coherent with arrivals by construction) plus
// HW-sleep backoff; release/acquire via __threadfence.
__device__ __forceinline__ void grid_barrier(unsigned* ctr) {
    __syncthreads();
    if (threadIdx.x == 0) {
        __threadfence();                                  // release prior stores to L2
        unsigned old = atomicAdd(ctr, 1u);
        unsigned target = (old & ~(unsigned)(NB - 1)) + (unsigned)NB;
        while ((int)(atomicAdd(ctr, 0u) - target) < 0) __nanosleep(64);
        __threadfence();                                  // acquire
    }
    __syncthreads();
}

__global__ __launch_bounds__(512, 1) void k_fused(
    const float* __restrict__ x, const float* __restrict__ wla,
    const float* __restrict__ wph, const float* __restrict__ c_star,
    const float* __restrict__ dt_star, const float* __restrict__ log_poles,
    const float* __restrict__ pole_w, const float* __restrict__ pole_b,
    float* __restrict__ out)
{
    __shared__ SMem sm;
    int bx = blockIdx.x;
    int tid = threadIdx.x;

    // ================= Phase 1: xsum + cpart (+ wsum on blocks 0..31) =================
    {
        int b = bx >> 4, sc = bx & 15;           // 16 s-chunks of 128 per batch
        int cg = tid >> 5, lane = tid & 31;      // 16 channel-pairs, 32 quads
        const float4* xb = (const float4*)x;
        float4 v0 = xb[(size_t)(b * CH + 2 * cg) * (SS / 4) + sc * 32 + lane];
        float4 v1 = xb[(size_t)(b * CH + 2 * cg + 1) * (SS / 4) + sc * 32 + lane];
        sm.p1.sacc[2 * cg][lane] = v0;
        sm.p1.sacc[2 * cg + 1][lane] = v1;
        float c0 = (v0.x + v0.y) + (v0.z + v0.w);
        float c1 = (v1.x + v1.y) + (v1.z + v1.w);
        #pragma unroll
        for (int d = 16; d >= 1; d >>= 1) {
            c0 += __shfl_xor_sync(0xffffffffu, c0, d);
            c1 += __shfl_xor_sync(0xffffffffu, c1, d);
        }
        if (lane == 0) {
            g_cpart[bx * 32 + 2 * cg] = c0;
            g_cpart[bx * 32 + 2 * cg + 1] = c1;
        }
        __syncthreads();
        if (tid < 128) {
            int qq = tid & 31, part = tid >> 5;
            float4 acc = make_float4(0.f, 0.f, 0.f, 0.f);
            #pragma unroll
            for (int c = 0; c < 8; c++) {
                float4 u = sm.p1.sacc[part * 8 + c][qq];
                acc.x += u.x; acc.y += u.y; acc.z += u.z; acc.w += u.w;
            }
            sm.p1.sacc2[part][qq] = acc;
        }
        __syncthreads();
        if (tid < 32) {
            float4 a0 = sm.p1.sacc2[0][tid], a1 = sm.p1.sacc2[1][tid];
            float4 a2 = sm.p1.sacc2[2][tid], a3 = sm.p1.sacc2[3][tid];
            a0.x += a1.x + a2.x + a3.x;
            a0.y += a1.y + a2.y + a3.y;
            a0.z += a1.z + a2.z + a3.z;
            a0.w += a1.w + a2.w + a3.w;
            ((float4*)g_xsum)[b * (SS / 4) + sc * 32 + tid] = a0;
        }
        // side job: wsum row k = bx for blocks 0..31
        if (bx < 32) {
            int k = bx, cc = tid >> 5, o = tid & 31;
            float s = 0.f;
            int idx = (k * CH + cc) * OC + o;
            s += (1.f / (1.f + expf(-wla[idx]))) * cosf(wph[idx]);
            idx = (k * CH + cc + 16) * OC + o;
            s += (1.f / (1.f + expf(-wla[idx]))) * cosf(wph[idx]);
            sm.p1.sws[cc][o] = s;
            __syncthreads();
            if (tid < 32) {
                float t = 0.f;
                #pragma unroll
                for (int j = 0; j < 16; j++) t += sm.p1.sws[j][tid];
                g_wsum[k * OC + tid] = t;
            }
        }
    }
    grid_barrier(&g_bar0);

    // ================= Phase 2: decay scans (blocks 0..15) =================
    if (bx < 16) {
        int b = bx >> 1;
        bool fwd = (bx & 1) == 0;
        if (tid < 256) {
            const float4* src = (const float4*)g_xsum + b * (SS / 4);
            sm.p2.xs4[tid]       = __ldcg(src + tid);
            sm.p2.xs4[tid + 256] = __ldcg(src + tid + 256);
            int c = tid & 31, r = tid >> 5;
            float s = 0.f;
            #pragma unroll
            for (int j = 0; j < 16; j++) s += __ldcg(&g_cpart[(r * 16 + j) * 32 + c]);
            sm.p2.sxm[c][r] = s;
        }
        __syncthreads();
        if (tid < 32) {
            float s = 0.f;
            #pragma unroll
            for (int r = 0; r < 8; r++) s += sm.p2.sxm[tid][r];
            sm.p2.sxm[tid][8] = s * (1.f / (float)(SB * SS));
        }
        __syncthreads();
        if (tid < 32) {
            int k = tid;
            float off = 0.f;
            #pragma unroll 8
            for (int cc = 0; cc < CH; cc++) off += sm.p2.sxm[cc][8] * pole_w[cc * KM + k];
            off = tanhf(off + pole_b[k]);
            float vv = log_poles[k] + 0.1f * off;
            float sp = fmaxf(vv, 0.f) + log1pf(expf(-fabsf(vv)));   // softplus
            float p = fminf(fmaxf(sp, 0.1f), 100.f);
            sm.p2.a[k]  = expf(-p * DF);
            sm.p2.aG[k] = expf(-p * DF * 64.f);
            if (bx == 0) {                       // b==0, fwd publishes
                g_poles[k] = p;
                g_a[k] = sm.p2.a[k];
                if (k == 0) {
                    float mx = c_star[0];
                    for (int i = 1; i < SB; i++) mx = fmaxf(mx, c_star[i]);
                    g_D = mx * dt_star[0];       // CAUSAL_SAFETY = 1
                }
            }
        }
        __syncthreads();

        int j = tid >> 3, m = tid & 7;           // chunk of 64 t, group of 4 modes
        float a0 = 0.f, a1 = 0.f, a2 = 0.f, a3 = 0.f;
        if (tid < 256) {
            a0 = sm.p2.a[4*m+0]; a1 = sm.p2.a[4*m+1];
            a2 = sm.p2.a[4*m+2]; a3 = sm.p2.a[4*m+3];
            const float4* c4 = sm.p2.xs4 + j * 16;
            float s0 = 0.f, s1 = 0.f, s2 = 0.f, s3 = 0.f;
            if (fwd) {
                #pragma unroll
                for (int i = 0; i < 16; i++) {
                    float4 v = c4[i];
                    s0=fmaf(a0,s0,v.x); s1=fmaf(a1,s1,v.x); s2=fmaf(a2,s2,v.x); s3=fmaf(a3,s3,v.x);
                    s0=fmaf(a0,s0,v.y); s1=fmaf(a1,s1,v.y); s2=fmaf(a2,s2,v.y); s3=fmaf(a3,s3,v.y);
                    s0=fmaf(a0,s0,v.z); s1=fmaf(a1,s1,v.z); s2=fmaf(a2,s2,v.z); s3=fmaf(a3,s3,v.z);
                    s0=fmaf(a0,s0,v.w); s1=fmaf(a1,s1,v.w); s2=fmaf(a2,s2,v.w); s3=fmaf(a3,s3,v.w);
                }
            } else {
                #pragma unroll
                for (int i = 15; i >= 0; i--) {
                    float4 v = c4[i];
                    s0=fmaf(a0,s0,v.w); s1=fmaf(a1,s1,v.w); s2=fmaf(a2,s2,v.w); s3=fmaf(a3,s3,v.w);
                    s0=fmaf(a0,s0,v.z); s1=fmaf(a1,s1,v.z); s2=fmaf(a2,s2,v.z); s3=fmaf(a3,s3,v.z);
                    s0=fmaf(a0,s0,v.y); s1=fmaf(a1,s1,v.y); s2=fmaf(a2,s2,v.y); s3=fmaf(a3,s3,v.y);
                    s0=fmaf(a0,s0,v.x); s1=fmaf(a1,s1,v.x); s2=fmaf(a2,s2,v.x); s3=fmaf(a3,s3,v.x);
                }
            }
            sm.p2.lc[j * 33 + 4*m+0] = s0; sm.p2.lc[j * 33 + 4*m+1] = s1;
            sm.p2.lc[j * 33 + 4*m+2] = s2; sm.p2.lc[j * 33 + 4*m+3] = s3;
        }
        __syncthreads();
        if (tid < 256) {                         // Kogge-Stone over chunks
            int w = tid >> 5, lane = tid & 31;
            int q = fwd ? lane : (31 - lane);
            #pragma unroll
            for (int i = 0; i < 4; i++) {
                int k = 4 * w + i;
                float v = sm.p2.lc[q * 33 + k];
                float Ap = sm.p2.aG[k];          // a^64
                #pragma unroll
                for (int d = 1; d < 32; d <<= 1) {
                    float up = __shfl_up_sync(0xffffffffu, v, d);
                    if (lane >= d) v = fmaf(Ap, up, v);
                    Ap = Ap * Ap;
                }
                float inc = __shfl_up_sync(0xffffffffu, v, 1);
                if (lane == 0) inc = 0.f;
                sm.p2.lc[q * 33 + k] = inc;
            }
        }
        __syncthreads();
        if (tid < 256) {                         // seeded pass 2, STG.128 into [b][t][k]
            const float4* c4 = sm.p2.xs4 + j * 16;
            float* Zt = (fwd ? g_P : g_Q) + (size_t)b * SS * KM;
            float s0 = sm.p2.lc[j * 33 + 4*m+0], s1 = sm.p2.lc[j * 33 + 4*m+1];
            float s2 = sm.p2.lc[j * 33 + 4*m+2], s3 = sm.p2.lc[j * 33 + 4*m+3];
            int t0 = j * 64;
            if (fwd) {
                #pragma unroll
                for (int i = 0; i < 16; i++) {
                    float4 v = c4[i];
                    s0=fmaf(a0,s0,v.x); s1=fmaf(a1,s1,v.x); s2=fmaf(a2,s2,v.x); s3=fmaf(a3,s3,v.x);
                    *(float4*)(Zt + (size_t)(t0 + 4*i + 0) * KM + 4*m) = make_float4(s0,s1,s2,s3);
                    s0=fmaf(a0,s0,v.y); s1=fmaf(a1,s1,v.y); s2=fmaf(a2,s2,v.y); s3=fmaf(a3,s3,v.y);
                    *(float4*)(Zt + (size_t)(t0 + 4*i + 1) * KM + 4*m) = make_float4(s0,s1,s2,s3);
                    s0=fmaf(a0,s0,v.z); s1=fmaf(a1,s1,v.z); s2=fmaf(a2,s2,v.z); s3=fmaf(a3,s3,v.z);
                    *(float4*)(Zt + (size_t)(t0 + 4*i + 2) * KM + 4*m) = make_float4(s0,s1,s2,s3);
                    s0=fmaf(a0,s0,v.w); s1=fmaf(a1,s1,v.w); s2=fmaf(a2,s2,v.w); s3=fmaf(a3,s3,v.w);
                    *(float4*)(Zt + (size_t)(t0 + 4*i + 3) * KM + 4*m) = make_float4(s0,s1,s2,s3);
                }
            } else {
                #pragma unroll
                for (int i = 15; i >= 0; i--) {
                    float4 v = c4[i];
                    s0=fmaf(a0,s0,v.w); s1=fmaf(a1,s1,v.w); s2=fmaf(a2,s2,v.w); s3=fmaf(a3,s3,v.w);
                    *(float4*)(Zt + (size_t)(t0 + 4*i + 3) * KM + 4*m) = make_float4(s0,s1,s2,s3);
                    s0=fmaf(a0,s0,v.z); s1=fmaf(a1,s1,v.z); s2=fmaf(a2,s2,v.z); s3=fmaf(a3,s3,v.z);
                    *(float4*)(Zt + (size_t)(t0 + 4*i + 2) * KM + 4*m) = make_float4(s0,s1,s2,s3);
                    s0=fmaf(a0,s0,v.y); s1=fmaf(a1,s1,v.y); s2=fmaf(a2,s2,v.y); s3=fmaf(a3,s3,v.y);
                    *(float4*)(Zt + (size_t)(t0 + 4*i + 1) * KM + 4*m) = make_float4(s0,s1,s2,s3);
                    s0=fmaf(a0,s0,v.x); s1=fmaf(a1,s1,v.x); s2=fmaf(a2,s2,v.x); s3=fmaf(a3,s3,v.x);
                    *(float4*)(Zt + (size_t)(t0 + 4*i + 0) * KM + 4*m) = make_float4(s0,s1,s2,s3);
                }
            }
        }
    }
    grid_barrier(&g_bar1);

    // ================= Phase 3: windows + z tiles + GEMV (all blocks, 4 tiles) =========
    {
        int b = bx >> 4;
        int s2 = tid >> 8, stid = tid & 255;     // two concurrent 256-thread tile groups
        int w = stid >> 5, lane = stid & 31;
        if (tid < 256) ((float4*)sm.p3.ws)[tid] = __ldcg((const float4*)g_wsum + tid);
        if (tid >= 256 && tid < 288) {
            int k = tid - 256;
            sm.p3.pol[k] = __ldcg(&g_poles[k]);
            sm.p3.aa[k]  = __ldcg(&g_a[k]);
        }
        __syncthreads();
        float Dv = __ldcg(&g_D);
        float ak = sm.p3.aa[lane];
        float ph = sm.p3.pol[lane] * DF;
        float inv_em = 1.f / expm1f(-ph);
        float kn = (float)lane * (1.0f / 31.0f);
        float filt = expf(-4.f * kn * kn);
        const float* Pb = g_P + (size_t)b * SS * KM;
        const float* Qb = g_Q + (size_t)b * SS * KM;

        #pragma unroll
        for (int it = 0; it < 2; it++) {
            int t0 = ((bx & 15) * 4 + it * 2 + s2) * 32;
            if (w == 1) {                        // exact float32 window search
                int tl = lane;
                int t = t0 + tl;
                float ct = coordf(t);
                int guess = (int)(Dv * 2047.0f) + 2;
                int hi = SS - 1 - t;
                int j = min(hi, max(0, guess));
                while (j > 0 && fabsf(coordf(t + j) - ct) > Dv) j--;
                while (j < hi && fabsf(coordf(t + j + 1) - ct) <= Dv) j++;
                sm.p3.smR[s2][tl] = j;
                hi = t;
                j = min(hi, max(0, guess));
                while (j > 0 && fabsf(coordf(t - j) - ct) > Dv) j--;
                while (j < hi && fabsf(coordf(t - j - 1) - ct) <= Dv) j++;
                sm.p3.smL[s2][tl] = j;
            }
            __syncthreads();
            #pragma unroll
            for (int q = 0; q < 4; q++) {        // phase A: rows tl = w + 8q, lane = k
                int tl = w + 8 * q;
                int t = t0 + tl;
                int mL = sm.p3.smL[s2][tl], mR = sm.p3.smR[s2][tl];
                float P  = __ldcg(&Pb[(size_t)t * KM + lane]);
                int tm = t - mL - 1;
                float Pm = (tm >= 0) ? __ldcg(&Pb[(size_t)tm * KM + lane]) : 0.f;
                float Qp = (t + 1 < SS) ? __ldcg(&Qb[(size_t)(t + 1) * KM + lane]) : 0.f;
                int tp = t + mR + 1;
                float Qm = (tp < SS) ? __ldcg(&Qb[(size_t)tp * KM + lane]) : 0.f;
                float cLe = expm1f(-ph * (float)(mL + 1));
                float cRe = expm1f(-ph * (float)(mR + 1));
                float norm = fmaxf(fmaf(cLe, inv_em, cRe * inv_em) - 1.f, 1e-8f);
                float L = fmaf(-(cLe + 1.f), Pm, P);
                float R = fmaf(-(cRe + 1.f), Qm, ak * Qp);
                sm.p3.zt[s2][tl * 32 + lane] = (L + R) * (filt / norm);
            }
            __syncthreads();
            #pragma unroll
            for (int q = 0; q < 4; q++) {        // phase B: GEMV, rows 4w..4w+3, lane = o
                int tl = w * 4 + q;
                const float4* zr = (const float4*)(sm.p3.zt[s2] + tl * 32);
                float acc = 0.f;
                #pragma unroll
                for (int p = 0; p < 8; p++) {
                    float4 zv = zr[p];
                    acc = fmaf(zv.x, sm.p3.ws[(p * 4 + 0) * OC + lane], acc);
                    acc = fmaf(zv.y, sm.p3.ws[(p * 4 + 1) * OC + lane], acc);
                    acc = fmaf(zv.z, sm.p3.ws[(p * 4 + 2) * OC + lane], acc);
                    acc = fmaf(zv.w, sm.p3.ws[(p * 4 + 3) * OC + lane], acc);
                }
                sm.p3.st[s2][tl * 33 + lane] = acc;
            }
            __syncthreads();
            int o = stid >> 3, i0 = (stid & 7) * 4;
            float4 r;
            r.x = sm.p3.st[s2][(i0 + 0) * 33 + o];
            r.y = sm.p3.st[s2][(i0 + 1) * 33 + o];
            r.z = sm.p3.st[s2][(i0 + 2) * 33 + o];
            r.w = sm.p3.st[s2][(i0 + 3) * 33 + o];
            *(float4*)(out + ((size_t)(b * OC + o)) * SS + t0 + i0) = r;
            __syncthreads();
        }
    }
}

extern "C" void kernel_launch(void* const* d_in, const int* in_sizes, int n_in,
                              void* d_out, int out_size) {
    // size-based input resolution
    int ix = -1, ic = -1, idt = -1, iwla = -1, iwph = -1, ilp = -1, ipw = -1, ipb = -1;
    for (int i = 0; i < n_in; i++) {
        int s = in_sizes[i];
        if (s == SB * CH * SS)      { if (ix  < 0) ix  = i; }
        else if (s == SB)           { if (ic  < 0) ic  = i; }
        else if (s == KM * CH * OC) { if (iwla < 0) iwla = i; else if (iwph < 0) iwph = i; }
        else if (s == CH * KM)      { if (ipw < 0) ipw = i; }
        else if (s == KM)           { if (ilp < 0) ilp = i; else if (ipb < 0) ipb = i; }
        else if (s == 1)            { if (idt < 0) idt = i; }
    }
    const float* x   = (const float*)d_in[ix];
    const float* cs  = (const float*)d_in[ic];
    const float* dt  = (const float*)d_in[idt];
    const float* wla = (const float*)d_in[iwla];
    const float* wph = (const float*)d_in[iwph];
    const float* lp  = (const float*)d_in[ilp];
    const float* pw  = (const float*)d_in[ipw];
    const float* pb  = (const float*)d_in[ipb];
    float* out = (float*)d_out;

    k_fused<<<NB, 512>>>(x, wla, wph, cs, dt, lp, pw, pb, out);
}

// round 10
// speedup vs baseline: 1.0241x; 1.0241x over previous
#include <cuda_runtime.h>
#include <math.h>

#define SB 8
#define CH 32
#define KM 32
#define OC 32
#define SS 2048
#define DF (1.0f/2047.0f)
#define NB 128

// ---- scratch (device globals: allocation-free rule) ----
__device__ __align__(16) float g_xsum[SB*SS];            // [b][s]
__device__ float g_cpart[NB*CH];                         // per-block per-channel partials
__device__ __align__(16) float g_P[(size_t)SB*SS*KM];    // [b][t][k] fwd decay scan
__device__ __align__(16) float g_Q[(size_t)SB*SS*KM];    // [b][t][k] bwd decay scan
__device__ __align__(16) float g_wsum[KM*OC];            // [k][o]
__device__ float g_segc[SB*2*4*KM];                      // [b][dir][tseg][k] segment carries
__device__ unsigned g_bar0, g_bar1, g_bar2;              // monotonic barrier counters

struct P1 { float4 sacc[32][32]; float4 sacc2[4][32]; float sws[16][32]; };
struct P2 { float lc[32*33]; };
struct P3 { float ws[KM*OC]; float zt[2][32*32]; float st[2][32*33];
            int smL[2][32]; int smR[2][32]; };
union __align__(16) SMem { P1 p1; P2 p2; P3 p3; };

// replicate reference float32 coords: linspace(0,1,2048)
__device__ __forceinline__ float coordf(int i) {
    return (i == SS - 1) ? 1.0f : ((float)i) * DF;
}

// Wrap-free monotonic grid barrier (proven in round 9): counter advances by
// exactly NB per launch; (old & ~(NB-1)) + NB is this cohort's release value.
// Safe across graph replays and ncu kernel-replay. L2-atomic spin + HW sleep.
__device__ __forceinline__ void grid_barrier(unsigned* ctr) {
    __syncthreads();
    if (threadIdx.x == 0) {
        __threadfence();                                  // release
        unsigned old = atomicAdd(ctr, 1u);
        unsigned target = (old & ~(unsigned)(NB - 1)) + (unsigned)NB;
        while ((int)(atomicAdd(ctr, 0u) - target) < 0) __nanosleep(64);
        __threadfence();                                  // acquire
    }
    __syncthreads();
}

__global__ __launch_bounds__(512, 1) void k_fused(
    const float* __restrict__ x, const float* __restrict__ wla,
    const float* __restrict__ wph, const float* __restrict__ c_star,
    const float* __restrict__ dt_star, const float* __restrict__ log_poles,
    const float* __restrict__ pole_w, const float* __restrict__ pole_b,
    float* __restrict__ out)
{
    __shared__ SMem sm;
    __shared__ float sh_red[32][9];                      // cpart reduce scratch
    __shared__ float sh_pol[KM], sh_aa[KM], sh_a16[KM];
    __shared__ float sh_D;
    int bx = blockIdx.x;
    int tid = threadIdx.x;

    // ================= Phase 1: xsum + cpart (+ wsum on blocks 0..31) =================
    {
        int b = bx >> 4, sc = bx & 15;           // 16 s-chunks of 128 per batch
        int cg = tid >> 5, lane = tid & 31;
        const float4* xb = (const float4*)x;
        float4 v0 = xb[(size_t)(b * CH + 2 * cg) * (SS / 4) + sc * 32 + lane];
        float4 v1 = xb[(size_t)(b * CH + 2 * cg + 1) * (SS / 4) + sc * 32 + lane];
        sm.p1.sacc[2 * cg][lane] = v0;
        sm.p1.sacc[2 * cg + 1][lane] = v1;
        float c0 = (v0.x + v0.y) + (v0.z + v0.w);
        float c1 = (v1.x + v1.y) + (v1.z + v1.w);
        #pragma unroll
        for (int d = 16; d >= 1; d >>= 1) {
            c0 += __shfl_xor_sync(0xffffffffu, c0, d);
            c1 += __shfl_xor_sync(0xffffffffu, c1, d);
        }
        if (lane == 0) {
            g_cpart[bx * 32 + 2 * cg] = c0;
            g_cpart[bx * 32 + 2 * cg + 1] = c1;
        }
        __syncthreads();
        if (tid < 128) {
            int qq = tid & 31, part = tid >> 5;
            float4 acc = make_float4(0.f, 0.f, 0.f, 0.f);
            #pragma unroll
            for (int c = 0; c < 8; c++) {
                float4 u = sm.p1.sacc[part * 8 + c][qq];
                acc.x += u.x; acc.y += u.y; acc.z += u.z; acc.w += u.w;
            }
            sm.p1.sacc2[part][qq] = acc;
        }
        __syncthreads();
        if (tid < 32) {
            float4 a0 = sm.p1.sacc2[0][tid], a1 = sm.p1.sacc2[1][tid];
            float4 a2 = sm.p1.sacc2[2][tid], a3 = sm.p1.sacc2[3][tid];
            a0.x += a1.x + a2.x + a3.x;
            a0.y += a1.y + a2.y + a3.y;
            a0.z += a1.z + a2.z + a3.z;
            a0.w += a1.w + a2.w + a3.w;
            ((float4*)g_xsum)[b * (SS / 4) + sc * 32 + tid] = a0;
        }
        if (bx < 32) {                           // wsum row k = bx
            int k = bx, cc = tid >> 5, o = tid & 31;
            float s = 0.f;
            int idx = (k * CH + cc) * OC + o;
            s += (1.f / (1.f + expf(-wla[idx]))) * cosf(wph[idx]);
            idx = (k * CH + cc + 16) * OC + o;
            s += (1.f / (1.f + expf(-wla[idx]))) * cosf(wph[idx]);
            sm.p1.sws[cc][o] = s;
            __syncthreads();
            if (tid < 32) {
                float t = 0.f;
                #pragma unroll
                for (int j = 0; j < 16; j++) t += sm.p1.sws[j][tid];
                g_wsum[k * OC + tid] = t;
            }
        }
    }
    grid_barrier(&g_bar0);

    // ============ Poles/D: every block, redundantly, from cpart in L2 ============
    if (tid < 256) {
        int c = tid & 31, r = tid >> 5;
        float s = 0.f;
        #pragma unroll
        for (int j = 0; j < 16; j++) s += __ldcg(&g_cpart[(r * 16 + j) * 32 + c]);
        sh_red[c][r] = s;
    }
    __syncthreads();
    if (tid < 32) {
        float s = 0.f;
        #pragma unroll
        for (int r = 0; r < 8; r++) s += sh_red[tid][r];
        sh_red[tid][8] = s * (1.f / (float)(SB * SS));
    }
    __syncthreads();
    if (tid < 32) {
        int k = tid;
        float off = 0.f;
        #pragma unroll 8
        for (int cc = 0; cc < CH; cc++) off += sh_red[cc][8] * pole_w[cc * KM + k];
        off = tanhf(off + pole_b[k]);
        float vv = log_poles[k] + 0.1f * off;
        float sp = fmaxf(vv, 0.f) + log1pf(expf(-fabsf(vv)));   // softplus
        float p = fminf(fmaxf(sp, 0.1f), 100.f);
        sh_pol[k] = p;
        sh_aa[k]  = expf(-p * DF);
        sh_a16[k] = expf(-p * DF * 16.f);
        if (k == 0) {
            float mx = c_star[0];
            for (int i = 1; i < SB; i++) mx = fmaxf(mx, c_star[i]);
            sh_D = mx * dt_star[0];              // CAUSAL_SAFETY = 1
        }
    }
    __syncthreads();

    // ======= Phase 2a: segmented scans, 64 blocks = (b, dir, tseg of 512 t) =======
    float4 xv[4];                                // 16 x values, persist across barrier
    float a0=0.f, a1=0.f, a2=0.f, a3=0.f;
    int p2j = tid >> 3, p2m = tid & 7;           // chunk of 16 t, kgroup of 4 modes
    if (bx < 64) {
        int b = bx >> 3;
        bool fwd = ((bx >> 2) & 1) == 0;
        int t0 = (bx & 3) * 512;
        if (tid < 256) {
            const float4* src = (const float4*)(g_xsum + b * SS + t0) + p2j * 4;
            xv[0] = __ldcg(src + 0); xv[1] = __ldcg(src + 1);
            xv[2] = __ldcg(src + 2); xv[3] = __ldcg(src + 3);
            a0 = sh_aa[4*p2m+0]; a1 = sh_aa[4*p2m+1];
            a2 = sh_aa[4*p2m+2]; a3 = sh_aa[4*p2m+3];
            float s0 = 0.f, s1 = 0.f, s2 = 0.f, s3 = 0.f;
            if (fwd) {
                #pragma unroll
                for (int i = 0; i < 4; i++) {
                    float4 v = xv[i];
                    s0=fmaf(a0,s0,v.x); s1=fmaf(a1,s1,v.x); s2=fmaf(a2,s2,v.x); s3=fmaf(a3,s3,v.x);
                    s0=fmaf(a0,s0,v.y); s1=fmaf(a1,s1,v.y); s2=fmaf(a2,s2,v.y); s3=fmaf(a3,s3,v.y);
                    s0=fmaf(a0,s0,v.z); s1=fmaf(a1,s1,v.z); s2=fmaf(a2,s2,v.z); s3=fmaf(a3,s3,v.z);
                    s0=fmaf(a0,s0,v.w); s1=fmaf(a1,s1,v.w); s2=fmaf(a2,s2,v.w); s3=fmaf(a3,s3,v.w);
                }
            } else {
                #pragma unroll
                for (int i = 3; i >= 0; i--) {
                    float4 v = xv[i];
                    s0=fmaf(a0,s0,v.w); s1=fmaf(a1,s1,v.w); s2=fmaf(a2,s2,v.w); s3=fmaf(a3,s3,v.w);
                    s0=fmaf(a0,s0,v.z); s1=fmaf(a1,s1,v.z); s2=fmaf(a2,s2,v.z); s3=fmaf(a3,s3,v.z);
                    s0=fmaf(a0,s0,v.y); s1=fmaf(a1,s1,v.y); s2=fmaf(a2,s2,v.y); s3=fmaf(a3,s3,v.y);
                    s0=fmaf(a0,s0,v.x); s1=fmaf(a1,s1,v.x); s2=fmaf(a2,s2,v.x); s3=fmaf(a3,s3,v.x);
                }
            }
            sm.p2.lc[p2j * 33 + 4*p2m+0] = s0; sm.p2.lc[p2j * 33 + 4*p2m+1] = s1;
            sm.p2.lc[p2j * 33 + 4*p2m+2] = s2; sm.p2.lc[p2j * 33 + 4*p2m+3] = s3;
        }
        __syncthreads();
        if (tid < 256) {                         // KS over 32 chunks (scan order)
            int w = tid >> 5, lane = tid & 31;
            int jt = fwd ? lane : (31 - lane);
            int dir = (bx >> 2) & 1;
            #pragma unroll
            for (int i = 0; i < 4; i++) {
                int k = 4 * w + i;
                float v = sm.p2.lc[jt * 33 + k];
                float Ap = sh_a16[k];
                #pragma unroll
                for (int d = 1; d < 32; d <<= 1) {
                    float up = __shfl_up_sync(0xffffffffu, v, d);
                    if (lane >= d) v = fmaf(Ap, up, v);
                    Ap = Ap * Ap;
                }
                if (lane == 31)                  // inclusive total = segment carry
                    g_segc[((b * 2 + dir) * 4 + (bx & 3)) * KM + k] = v;
                float inc = __shfl_up_sync(0xffffffffu, v, 1);
                if (lane == 0) inc = 0.f;
                sm.p2.lc[jt * 33 + k] = inc;     // local exclusive prefix
            }
        }
    }
    grid_barrier(&g_bar1);

    // ======= Phase 2b: seed from segment carries, seeded store pass =======
    if (bx < 64 && tid < 256) {
        int b = bx >> 3;
        int dir = (bx >> 2) & 1;
        bool fwd = dir == 0;
        int tseg = bx & 3;
        int t0 = tseg * 512;
        float A16_0 = sh_a16[4*p2m+0], A16_1 = sh_a16[4*p2m+1];
        float A16_2 = sh_a16[4*p2m+2], A16_3 = sh_a16[4*p2m+3];
        // a^512 = (a^16)^32 via 5 squarings
        float A5_0 = A16_0, A5_1 = A16_1, A5_2 = A16_2, A5_3 = A16_3;
        #pragma unroll
        for (int q = 0; q < 5; q++) { A5_0*=A5_0; A5_1*=A5_1; A5_2*=A5_2; A5_3*=A5_3; }
        // segment seed: combine upstream segment carries in scan order
        float e0 = 0.f, e1 = 0.f, e2 = 0.f, e3 = 0.f;
        const float* segb = g_segc + (b * 2 + dir) * 4 * KM;
        if (fwd) {
            for (int s = 0; s < tseg; s++) {
                e0 = fmaf(A5_0, e0, __ldcg(&segb[s * KM + 4*p2m+0]));
                e1 = fmaf(A5_1, e1, __ldcg(&segb[s * KM + 4*p2m+1]));
                e2 = fmaf(A5_2, e2, __ldcg(&segb[s * KM + 4*p2m+2]));
                e3 = fmaf(A5_3, e3, __ldcg(&segb[s * KM + 4*p2m+3]));
            }
        } else {
            for (int s = 3; s > tseg; s--) {
                e0 = fmaf(A5_0, e0, __ldcg(&segb[s * KM + 4*p2m+0]));
                e1 = fmaf(A5_1, e1, __ldcg(&segb[s * KM + 4*p2m+1]));
                e2 = fmaf(A5_2, e2, __ldcg(&segb[s * KM + 4*p2m+2]));
                e3 = fmaf(A5_3, e3, __ldcg(&segb[s * KM + 4*p2m+3]));
            }
        }
        // a^(16*q) for my chunk's scan position q, by binary powering
        int qj = fwd ? p2j : (31 - p2j);
        float r0 = 1.f, r1 = 1.f, r2 = 1.f, r3 = 1.f;
        float pw0 = A16_0, pw1 = A16_1, pw2 = A16_2, pw3 = A16_3;
        #pragma unroll
        for (int bit = 0; bit < 5; bit++) {
            if ((qj >> bit) & 1) { r0*=pw0; r1*=pw1; r2*=pw2; r3*=pw3; }
            pw0*=pw0; pw1*=pw1; pw2*=pw2; pw3*=pw3;
        }
        float s0 = fmaf(r0, e0, sm.p2.lc[p2j * 33 + 4*p2m+0]);
        float s1 = fmaf(r1, e1, sm.p2.lc[p2j * 33 + 4*p2m+1]);
        float s2 = fmaf(r2, e2, sm.p2.lc[p2j * 33 + 4*p2m+2]);
        float s3 = fmaf(r3, e3, sm.p2.lc[p2j * 33 + 4*p2m+3]);
        float* Zt = (fwd ? g_P : g_Q) + (size_t)b * SS * KM + (size_t)(t0 + p2j * 16) * KM;
        if (fwd) {
            #pragma unroll
            for (int i = 0; i < 4; i++) {
                float4 v = xv[i];
                s0=fmaf(a0,s0,v.x); s1=fmaf(a1,s1,v.x); s2=fmaf(a2,s2,v.x); s3=fmaf(a3,s3,v.x);
                *(float4*)(Zt + (4*i + 0) * KM + 4*p2m) = make_float4(s0,s1,s2,s3);
                s0=fmaf(a0,s0,v.y); s1=fmaf(a1,s1,v.y); s2=fmaf(a2,s2,v.y); s3=fmaf(a3,s3,v.y);
                *(float4*)(Zt + (4*i + 1) * KM + 4*p2m) = make_float4(s0,s1,s2,s3);
                s0=fmaf(a0,s0,v.z); s1=fmaf(a1,s1,v.z); s2=fmaf(a2,s2,v.z); s3=fmaf(a3,s3,v.z);
                *(float4*)(Zt + (4*i + 2) * KM + 4*p2m) = make_float4(s0,s1,s2,s3);
                s0=fmaf(a0,s0,v.w); s1=fmaf(a1,s1,v.w); s2=fmaf(a2,s2,v.w); s3=fmaf(a3,s3,v.w);
                *(float4*)(Zt + (4*i + 3) * KM + 4*p2m) = make_float4(s0,s1,s2,s3);
            }
        } else {
            #pragma unroll
            for (int i = 3; i >= 0; i--) {
                float4 v = xv[i];
                s0=fmaf(a0,s0,v.w); s1=fmaf(a1,s1,v.w); s2=fmaf(a2,s2,v.w); s3=fmaf(a3,s3,v.w);
                *(float4*)(Zt + (4*i + 3) * KM + 4*p2m) = make_float4(s0,s1,s2,s3);
                s0=fmaf(a0,s0,v.z); s1=fmaf(a1,s1,v.z); s2=fmaf(a2,s2,v.z); s3=fmaf(a3,s3,v.z);
                *(float4*)(Zt + (4*i + 2) * KM + 4*p2m) = make_float4(s0,s1,s2,s3);
                s0=fmaf(a0,s0,v.y); s1=fmaf(a1,s1,v.y); s2=fmaf(a2,s2,v.y); s3=fmaf(a3,s3,v.y);
                *(float4*)(Zt + (4*i + 1) * KM + 4*p2m) = make_float4(s0,s1,s2,s3);
                s0=fmaf(a0,s0,v.x); s1=fmaf(a1,s1,v.x); s2=fmaf(a2,s2,v.x); s3=fmaf(a3,s3,v.x);
                *(float4*)(Zt + (4*i + 0) * KM + 4*p2m) = make_float4(s0,s1,s2,s3);
            }
        }
    }
    grid_barrier(&g_bar2);

    // ================= Phase 3: windows + z tiles + GEMV (all blocks) =================
    {
        int b = bx >> 4;
        int s2 = tid >> 8, stid = tid & 255;
        int w = stid >> 5, lane = stid & 31;
        if (tid < 256) ((float4*)sm.p3.ws)[tid] = __ldcg((const float4*)g_wsum + tid);
        __syncthreads();
        float Dv = sh_D;
        float ak = sh_aa[lane];
        float ph = sh_pol[lane] * DF;
        float inv_em = 1.f / expm1f(-ph);
        float kn = (float)lane * (1.0f / 31.0f);
        float filt = expf(-4.f * kn * kn);
        const float* Pb = g_P + (size_t)b * SS * KM;
        const float* Qb = g_Q + (size_t)b * SS * KM;

        #pragma unroll
        for (int it = 0; it < 2; it++) {
            int t0 = ((bx & 15) * 4 + it * 2 + s2) * 32;
            if (w == 1) {                        // exact float32 window search
                int tl = lane;
                int t = t0 + tl;
                float ct = coordf(t);
                int guess = (int)(Dv * 2047.0f) + 2;
                int hi = SS - 1 - t;
                int j = min(hi, max(0, guess));
                while (j > 0 && fabsf(coordf(t + j) - ct) > Dv) j--;
                while (j < hi && fabsf(coordf(t + j + 1) - ct) <= Dv) j++;
                sm.p3.smR[s2][tl] = j;
                hi = t;
                j = min(hi, max(0, guess));
                while (j > 0 && fabsf(coordf(t - j) - ct) > Dv) j--;
                while (j < hi && fabsf(coordf(t - j - 1) - ct) <= Dv) j++;
                sm.p3.smL[s2][tl] = j;
            }
            __syncthreads();
            #pragma unroll
            for (int q = 0; q < 4; q++) {        // phase A: rows tl = w + 8q, lane = k
                int tl = w + 8 * q;
                int t = t0 + tl;
                int mL = sm.p3.smL[s2][tl], mR = sm.p3.smR[s2][tl];
                float P  = __ldcg(&Pb[(size_t)t * KM + lane]);
                int tm = t - mL - 1;
                float Pm = (tm >= 0) ? __ldcg(&Pb[(size_t)tm * KM + lane]) : 0.f;
                float Qp = (t + 1 < SS) ? __ldcg(&Qb[(size_t)(t + 1) * KM + lane]) : 0.f;
                int tp = t + mR + 1;
                float Qm = (tp < SS) ? __ldcg(&Qb[(size_t)tp * KM + lane]) : 0.f;
                float cLe = expm1f(-ph * (float)(mL + 1));
                float cRe = expm1f(-ph * (float)(mR + 1));
                float norm = fmaxf(fmaf(cLe, inv_em, cRe * inv_em) - 1.f, 1e-8f);
                float L = fmaf(-(cLe + 1.f), Pm, P);
                float R = fmaf(-(cRe + 1.f), Qm, ak * Qp);
                sm.p3.zt[s2][tl * 32 + lane] = (L + R) * (filt / norm);
            }
            __syncthreads();
            #pragma unroll
            for (int q = 0; q < 4; q++) {        // phase B: GEMV
                int tl = w * 4 + q;
                const float4* zr = (const float4*)(sm.p3.zt[s2] + tl * 32);
                float acc = 0.f;
                #pragma unroll
                for (int p = 0; p < 8; p++) {
                    float4 zv = zr[p];
                    acc = fmaf(zv.x, sm.p3.ws[(p * 4 + 0) * OC + lane], acc);
                    acc = fmaf(zv.y, sm.p3.ws[(p * 4 + 1) * OC + lane], acc);
                    acc = fmaf(zv.z, sm.p3.ws[(p * 4 + 2) * OC + lane], acc);
                    acc = fmaf(zv.w, sm.p3.ws[(p * 4 + 3) * OC + lane], acc);
                }
                sm.p3.st[s2][tl * 33 + lane] = acc;
            }
            __syncthreads();
            int o = stid >> 3, i0 = (stid & 7) * 4;
            float4 r;
            r.x = sm.p3.st[s2][(i0 + 0) * 33 + o];
            r.y = sm.p3.st[s2][(i0 + 1) * 33 + o];
            r.z = sm.p3.st[s2][(i0 + 2) * 33 + o];
            r.w = sm.p3.st[s2][(i0 + 3) * 33 + o];
            *(float4*)(out + ((size_t)(b * OC + o)) * SS + t0 + i0) = r;
            __syncthreads();
        }
    }
}

extern "C" void kernel_launch(void* const* d_in, const int* in_sizes, int n_in,
                              void* d_out, int out_size) {
    // size-based input resolution
    int ix = -1, ic = -1, idt = -1, iwla = -1, iwph = -1, ilp = -1, ipw = -1, ipb = -1;
    for (int i = 0; i < n_in; i++) {
        int s = in_sizes[i];
        if (s == SB * CH * SS)      { if (ix  < 0) ix  = i; }
        else if (s == SB)           { if (ic  < 0) ic  = i; }
        else if (s == KM * CH * OC) { if (iwla < 0) iwla = i; else if (iwph < 0) iwph = i; }
        else if (s == CH * KM)      { if (ipw < 0) ipw = i; }
        else if (s == KM)           { if (ilp < 0) ilp = i; else if (ipb < 0) ipb = i; }
        else if (s == 1)            { if (idt < 0) idt = i; }
    }
    const float* x   = (const float*)d_in[ix];
    const float* cs  = (const float*)d_in[ic];
    const float* dt  = (const float*)d_in[idt];
    const float* wla = (const float*)d_in[iwla];
    const float* wph = (const float*)d_in[iwph];
    const float* lp  = (const float*)d_in[ilp];
    const float* pw  = (const float*)d_in[ipw];
    const float* pb  = (const float*)d_in[ipb];
    float* out = (float*)d_out;

    k_fused<<<NB, 512>>>(x, wla, wph, cs, dt, lp, pw, pb, out);
}

// round 11
// speedup vs baseline: 1.0256x; 1.0014x over previous
#include <cuda_runtime.h>
#include <math.h>

#define SB 8
#define CH 32
#define KM 32
#define OC 32
#define SS 2048
#define DF (1.0f/2047.0f)
#define NB 128

// ---- scratch (device globals: allocation-free rule) ----
__device__ __align__(16) float g_xsum[SB*SS];            // [b][s]
__device__ float g_cpart[NB*CH];                         // per-block per-channel partials
__device__ __align__(16) float g_P[(size_t)SB*SS*KM];    // [b][t][k] fwd decay scan
__device__ __align__(16) float g_Q[(size_t)SB*SS*KM];    // [b][t][k] bwd decay scan
__device__ __align__(16) float g_wsum[KM*OC];            // [k][o]
__device__ float g_segc[SB*2*4*KM];                      // [b][dir][tseg][k] segment carries
__device__ unsigned g_bar0, g_bar1, g_bar2;              // monotonic barrier counters

struct P1 { float4 sacc[32][32]; float4 sacc2[4][32]; float sws[16][32]; };
struct P2 { float lc[32*33]; };
struct P3 { float ws[KM*OC]; float zt[2][32*32]; float st[2][32*33];
            int smL[2][32]; int smR[2][32]; };
union __align__(16) SMem { P1 p1; P2 p2; P3 p3; };

// replicate reference float32 coords: linspace(0,1,2048)
__device__ __forceinline__ float coordf(int i) {
    return (i == SS - 1) ? 1.0f : ((float)i) * DF;
}

// Guaranteed-reissue L2 read (no CSE/hoist): polls the line where atomics commit.
__device__ __forceinline__ unsigned ldcg_u32(const unsigned* p) {
    unsigned v;
    asm volatile("ld.global.cg.u32 %0, [%1];" : "=r"(v) : "l"(p) : "memory");
    return v;
}

// Wrap-free monotonic grid barrier. Counter advances by exactly NB per launch;
// (old & ~(NB-1)) + NB is this cohort's release value — safe across graph
// replays and ncu kernel-replay. Arrival = L2 atomic; SPIN = plain .cg load
// (atomics commit at L2, so the load is coherent with arrivals) — avoids the
// same-address RMW serialization storm of an atomic-based spin.
__device__ __forceinline__ void grid_barrier(unsigned* ctr) {
    __syncthreads();
    if (threadIdx.x == 0) {
        __threadfence();                                  // release
        unsigned old = atomicAdd(ctr, 1u);
        unsigned target = (old & ~(unsigned)(NB - 1)) + (unsigned)NB;
        while ((int)(ldcg_u32(ctr) - target) < 0) __nanosleep(32);
        __threadfence();                                  // acquire
    }
    __syncthreads();
}

__global__ __launch_bounds__(512, 1) void k_fused(
    const float* __restrict__ x, const float* __restrict__ wla,
    const float* __restrict__ wph, const float* __restrict__ c_star,
    const float* __restrict__ dt_star, const float* __restrict__ log_poles,
    const float* __restrict__ pole_w, const float* __restrict__ pole_b,
    float* __restrict__ out)
{
    __shared__ SMem sm;
    __shared__ float sh_red[32][9];                      // cpart reduce scratch
    __shared__ float sh_pol[KM], sh_aa[KM], sh_a16[KM];
    __shared__ float sh_D;
    int bx = blockIdx.x;
    int tid = threadIdx.x;

    // ================= Phase 1: xsum + cpart (+ wsum on blocks 0..31) =================
    {
        int b = bx >> 4, sc = bx & 15;           // 16 s-chunks of 128 per batch
        int cg = tid >> 5, lane = tid & 31;
        const float4* xb = (const float4*)x;
        float4 v0 = xb[(size_t)(b * CH + 2 * cg) * (SS / 4) + sc * 32 + lane];
        float4 v1 = xb[(size_t)(b * CH + 2 * cg + 1) * (SS / 4) + sc * 32 + lane];
        sm.p1.sacc[2 * cg][lane] = v0;
        sm.p1.sacc[2 * cg + 1][lane] = v1;
        float c0 = (v0.x + v0.y) + (v0.z + v0.w);
        float c1 = (v1.x + v1.y) + (v1.z + v1.w);
        #pragma unroll
        for (int d = 16; d >= 1; d >>= 1) {
            c0 += __shfl_xor_sync(0xffffffffu, c0, d);
            c1 += __shfl_xor_sync(0xffffffffu, c1, d);
        }
        if (lane == 0) {
            g_cpart[bx * 32 + 2 * cg] = c0;
            g_cpart[bx * 32 + 2 * cg + 1] = c1;
        }
        __syncthreads();
        if (tid < 128) {
            int qq = tid & 31, part = tid >> 5;
            float4 acc = make_float4(0.f, 0.f, 0.f, 0.f);
            #pragma unroll
            for (int c = 0; c < 8; c++) {
                float4 u = sm.p1.sacc[part * 8 + c][qq];
                acc.x += u.x; acc.y += u.y; acc.z += u.z; acc.w += u.w;
            }
            sm.p1.sacc2[part][qq] = acc;
        }
        __syncthreads();
        if (tid < 32) {
            float4 a0 = sm.p1.sacc2[0][tid], a1 = sm.p1.sacc2[1][tid];
            float4 a2 = sm.p1.sacc2[2][tid], a3 = sm.p1.sacc2[3][tid];
            a0.x += a1.x + a2.x + a3.x;
            a0.y += a1.y + a2.y + a3.y;
            a0.z += a1.z + a2.z + a3.z;
            a0.w += a1.w + a2.w + a3.w;
            ((float4*)g_xsum)[b * (SS / 4) + sc * 32 + tid] = a0;
        }
        if (bx < 32) {                           // wsum row k = bx
            int k = bx, cc = tid >> 5, o = tid & 31;
            float s = 0.f;
            int idx = (k * CH + cc) * OC + o;
            s += (1.f / (1.f + expf(-wla[idx]))) * cosf(wph[idx]);
            idx = (k * CH + cc + 16) * OC + o;
            s += (1.f / (1.f + expf(-wla[idx]))) * cosf(wph[idx]);
            sm.p1.sws[cc][o] = s;
            __syncthreads();
            if (tid < 32) {
                float t = 0.f;
                #pragma unroll
                for (int j = 0; j < 16; j++) t += sm.p1.sws[j][tid];
                g_wsum[k * OC + tid] = t;
            }
        }
    }
    grid_barrier(&g_bar0);

    // ============ Poles/D: every block, redundantly, from cpart in L2 ============
    if (tid < 256) {
        int c = tid & 31, r = tid >> 5;
        float s = 0.f;
        #pragma unroll
        for (int j = 0; j < 16; j++) s += __ldcg(&g_cpart[(r * 16 + j) * 32 + c]);
        sh_red[c][r] = s;
    }
    __syncthreads();
    if (tid < 32) {
        float s = 0.f;
        #pragma unroll
        for (int r = 0; r < 8; r++) s += sh_red[tid][r];
        sh_red[tid][8] = s * (1.f / (float)(SB * SS));
    }
    __syncthreads();
    if (tid < 32) {
        int k = tid;
        float off = 0.f;
        #pragma unroll 8
        for (int cc = 0; cc < CH; cc++) off += sh_red[cc][8] * pole_w[cc * KM + k];
        off = tanhf(off + pole_b[k]);
        float vv = log_poles[k] + 0.1f * off;
        float sp = fmaxf(vv, 0.f) + log1pf(expf(-fabsf(vv)));   // softplus
        float p = fminf(fmaxf(sp, 0.1f), 100.f);
        sh_pol[k] = p;
        sh_aa[k]  = expf(-p * DF);
        sh_a16[k] = expf(-p * DF * 16.f);
        if (k == 0) {
            float mx = c_star[0];
            for (int i = 1; i < SB; i++) mx = fmaxf(mx, c_star[i]);
            sh_D = mx * dt_star[0];              // CAUSAL_SAFETY = 1
        }
    }
    __syncthreads();

    // ======= Phase 2a: segmented scans, 64 blocks = (b, dir, tseg of 512 t) =======
    float4 xv[4];                                // 16 x values, persist across barrier
    float a0=0.f, a1=0.f, a2=0.f, a3=0.f;
    int p2j = tid >> 3, p2m = tid & 7;           // chunk of 16 t, kgroup of 4 modes
    if (bx < 64) {
        int b = bx >> 3;
        bool fwd = ((bx >> 2) & 1) == 0;
        int t0 = (bx & 3) * 512;
        if (tid < 256) {
            const float4* src = (const float4*)(g_xsum + b * SS + t0) + p2j * 4;
            xv[0] = __ldcg(src + 0); xv[1] = __ldcg(src + 1);
            xv[2] = __ldcg(src + 2); xv[3] = __ldcg(src + 3);
            a0 = sh_aa[4*p2m+0]; a1 = sh_aa[4*p2m+1];
            a2 = sh_aa[4*p2m+2]; a3 = sh_aa[4*p2m+3];
            float s0 = 0.f, s1 = 0.f, s2 = 0.f, s3 = 0.f;
            if (fwd) {
                #pragma unroll
                for (int i = 0; i < 4; i++) {
                    float4 v = xv[i];
                    s0=fmaf(a0,s0,v.x); s1=fmaf(a1,s1,v.x); s2=fmaf(a2,s2,v.x); s3=fmaf(a3,s3,v.x);
                    s0=fmaf(a0,s0,v.y); s1=fmaf(a1,s1,v.y); s2=fmaf(a2,s2,v.y); s3=fmaf(a3,s3,v.y);
                    s0=fmaf(a0,s0,v.z); s1=fmaf(a1,s1,v.z); s2=fmaf(a2,s2,v.z); s3=fmaf(a3,s3,v.z);
                    s0=fmaf(a0,s0,v.w); s1=fmaf(a1,s1,v.w); s2=fmaf(a2,s2,v.w); s3=fmaf(a3,s3,v.w);
                }
            } else {
                #pragma unroll
                for (int i = 3; i >= 0; i--) {
                    float4 v = xv[i];
                    s0=fmaf(a0,s0,v.w); s1=fmaf(a1,s1,v.w); s2=fmaf(a2,s2,v.w); s3=fmaf(a3,s3,v.w);
                    s0=fmaf(a0,s0,v.z); s1=fmaf(a1,s1,v.z); s2=fmaf(a2,s2,v.z); s3=fmaf(a3,s3,v.z);
                    s0=fmaf(a0,s0,v.y); s1=fmaf(a1,s1,v.y); s2=fmaf(a2,s2,v.y); s3=fmaf(a3,s3,v.y);
                    s0=fmaf(a0,s0,v.x); s1=fmaf(a1,s1,v.x); s2=fmaf(a2,s2,v.x); s3=fmaf(a3,s3,v.x);
                }
            }
            sm.p2.lc[p2j * 33 + 4*p2m+0] = s0; sm.p2.lc[p2j * 33 + 4*p2m+1] = s1;
            sm.p2.lc[p2j * 33 + 4*p2m+2] = s2; sm.p2.lc[p2j * 33 + 4*p2m+3] = s3;
        }
        __syncthreads();
        if (tid < 256) {                         // KS over 32 chunks (scan order)
            int w = tid >> 5, lane = tid & 31;
            int jt = fwd ? lane : (31 - lane);
            int dir = (bx >> 2) & 1;
            #pragma unroll
            for (int i = 0; i < 4; i++) {
                int k = 4 * w + i;
                float v = sm.p2.lc[jt * 33 + k];
                float Ap = sh_a16[k];
                #pragma unroll
                for (int d = 1; d < 32; d <<= 1) {
                    float up = __shfl_up_sync(0xffffffffu, v, d);
                    if (lane >= d) v = fmaf(Ap, up, v);
                    Ap = Ap * Ap;
                }
                if (lane == 31)                  // inclusive total = segment carry
                    g_segc[((b * 2 + dir) * 4 + (bx & 3)) * KM + k] = v;
                float inc = __shfl_up_sync(0xffffffffu, v, 1);
                if (lane == 0) inc = 0.f;
                sm.p2.lc[jt * 33 + k] = inc;     // local exclusive prefix
            }
        }
    }
    grid_barrier(&g_bar1);

    // ======= Phase 2b: seed from segment carries, seeded store pass =======
    if (bx < 64 && tid < 256) {
        int b = bx >> 3;
        int dir = (bx >> 2) & 1;
        bool fwd = dir == 0;
        int tseg = bx & 3;
        int t0 = tseg * 512;
        float A16_0 = sh_a16[4*p2m+0], A16_1 = sh_a16[4*p2m+1];
        float A16_2 = sh_a16[4*p2m+2], A16_3 = sh_a16[4*p2m+3];
        // a^512 = (a^16)^32 via 5 squarings
        float A5_0 = A16_0, A5_1 = A16_1, A5_2 = A16_2, A5_3 = A16_3;
        #pragma unroll
        for (int q = 0; q < 5; q++) { A5_0*=A5_0; A5_1*=A5_1; A5_2*=A5_2; A5_3*=A5_3; }
        // segment seed: combine upstream segment carries in scan order
        float e0 = 0.f, e1 = 0.f, e2 = 0.f, e3 = 0.f;
        const float* segb = g_segc + (b * 2 + dir) * 4 * KM;
        if (fwd) {
            for (int s = 0; s < tseg; s++) {
                e0 = fmaf(A5_0, e0, __ldcg(&segb[s * KM + 4*p2m+0]));
                e1 = fmaf(A5_1, e1, __ldcg(&segb[s * KM + 4*p2m+1]));
                e2 = fmaf(A5_2, e2, __ldcg(&segb[s * KM + 4*p2m+2]));
                e3 = fmaf(A5_3, e3, __ldcg(&segb[s * KM + 4*p2m+3]));
            }
        } else {
            for (int s = 3; s > tseg; s--) {
                e0 = fmaf(A5_0, e0, __ldcg(&segb[s * KM + 4*p2m+0]));
                e1 = fmaf(A5_1, e1, __ldcg(&segb[s * KM + 4*p2m+1]));
                e2 = fmaf(A5_2, e2, __ldcg(&segb[s * KM + 4*p2m+2]));
                e3 = fmaf(A5_3, e3, __ldcg(&segb[s * KM + 4*p2m+3]));
            }
        }
        // a^(16*q) for my chunk's scan position q, by binary powering
        int qj = fwd ? p2j : (31 - p2j);
        float r0 = 1.f, r1 = 1.f, r2 = 1.f, r3 = 1.f;
        float pw0 = A16_0, pw1 = A16_1, pw2 = A16_2, pw3 = A16_3;
        #pragma unroll
        for (int bit = 0; bit < 5; bit++) {
            if ((qj >> bit) & 1) { r0*=pw0; r1*=pw1; r2*=pw2; r3*=pw3; }
            pw0*=pw0; pw1*=pw1; pw2*=pw2; pw3*=pw3;
        }
        float s0 = fmaf(r0, e0, sm.p2.lc[p2j * 33 + 4*p2m+0]);
        float s1 = fmaf(r1, e1, sm.p2.lc[p2j * 33 + 4*p2m+1]);
        float s2 = fmaf(r2, e2, sm.p2.lc[p2j * 33 + 4*p2m+2]);
        float s3 = fmaf(r3, e3, sm.p2.lc[p2j * 33 + 4*p2m+3]);
        float* Zt = (fwd ? g_P : g_Q) + (size_t)b * SS * KM + (size_t)(t0 + p2j * 16) * KM;
        if (fwd) {
            #pragma unroll
            for (int i = 0; i < 4; i++) {
                float4 v = xv[i];
                s0=fmaf(a0,s0,v.x); s1=fmaf(a1,s1,v.x); s2=fmaf(a2,s2,v.x); s3=fmaf(a3,s3,v.x);
                *(float4*)(Zt + (4*i + 0) * KM + 4*p2m) = make_float4(s0,s1,s2,s3);
                s0=fmaf(a0,s0,v.y); s1=fmaf(a1,s1,v.y); s2=fmaf(a2,s2,v.y); s3=fmaf(a3,s3,v.y);
                *(float4*)(Zt + (4*i + 1) * KM + 4*p2m) = make_float4(s0,s1,s2,s3);
                s0=fmaf(a0,s0,v.z); s1=fmaf(a1,s1,v.z); s2=fmaf(a2,s2,v.z); s3=fmaf(a3,s3,v.z);
                *(float4*)(Zt + (4*i + 2) * KM + 4*p2m) = make_float4(s0,s1,s2,s3);
                s0=fmaf(a0,s0,v.w); s1=fmaf(a1,s1,v.w); s2=fmaf(a2,s2,v.w); s3=fmaf(a3,s3,v.w);
                *(float4*)(Zt + (4*i + 3) * KM + 4*p2m) = make_float4(s0,s1,s2,s3);
            }
        } else {
            #pragma unroll
            for (int i = 3; i >= 0; i--) {
                float4 v = xv[i];
                s0=fmaf(a0,s0,v.w); s1=fmaf(a1,s1,v.w); s2=fmaf(a2,s2,v.w); s3=fmaf(a3,s3,v.w);
                *(float4*)(Zt + (4*i + 3) * KM + 4*p2m) = make_float4(s0,s1,s2,s3);
                s0=fmaf(a0,s0,v.z); s1=fmaf(a1,s1,v.z); s2=fmaf(a2,s2,v.z); s3=fmaf(a3,s3,v.z);
                *(float4*)(Zt + (4*i + 2) * KM + 4*p2m) = make_float4(s0,s1,s2,s3);
                s0=fmaf(a0,s0,v.y); s1=fmaf(a1,s1,v.y); s2=fmaf(a2,s2,v.y); s3=fmaf(a3,s3,v.y);
                *(float4*)(Zt + (4*i + 1) * KM + 4*p2m) = make_float4(s0,s1,s2,s3);
                s0=fmaf(a0,s0,v.x); s1=fmaf(a1,s1,v.x); s2=fmaf(a2,s2,v.x); s3=fmaf(a3,s3,v.x);
                *(float4*)(Zt + (4*i + 0) * KM + 4*p2m) = make_float4(s0,s1,s2,s3);
            }
        }
    }
    grid_barrier(&g_bar2);

    // ================= Phase 3: windows + z tiles + GEMV (all blocks) =================
    {
        int b = bx >> 4;
        int s2 = tid >> 8, stid = tid & 255;
        int w = stid >> 5, lane = stid & 31;
        if (tid < 256) ((float4*)sm.p3.ws)[tid] = __ldcg((const float4*)g_wsum + tid);
        __syncthreads();
        float Dv = sh_D;
        float ak = sh_aa[lane];
        float ph = sh_pol[lane] * DF;
        float inv_em = 1.f / expm1f(-ph);
        float kn = (float)lane * (1.0f / 31.0f);
        float filt = expf(-4.f * kn * kn);
        const float* Pb = g_P + (size_t)b * SS * KM;
        const float* Qb = g_Q + (size_t)b * SS * KM;

        #pragma unroll
        for (int it = 0; it < 2; it++) {
            int t0 = ((bx & 15) * 4 + it * 2 + s2) * 32;
            if (w == 1) {                        // exact float32 window search
                int tl = lane;
                int t = t0 + tl;
                float ct = coordf(t);
                int guess = (int)(Dv * 2047.0f) + 2;
                int hi = SS - 1 - t;
                int j = min(hi, max(0, guess));
                while (j > 0 && fabsf(coordf(t + j) - ct) > Dv) j--;
                while (j < hi && fabsf(coordf(t + j + 1) - ct) <= Dv) j++;
                sm.p3.smR[s2][tl] = j;
                hi = t;
                j = min(hi, max(0, guess));
                while (j > 0 && fabsf(coordf(t - j) - ct) > Dv) j--;
                while (j < hi && fabsf(coordf(t - j - 1) - ct) <= Dv) j++;
                sm.p3.smL[s2][tl] = j;
            }
            __syncthreads();
            #pragma unroll
            for (int q = 0; q < 4; q++) {        // phase A: rows tl = w + 8q, lane = k
                int tl = w + 8 * q;
                int t = t0 + tl;
                int mL = sm.p3.smL[s2][tl], mR = sm.p3.smR[s2][tl];
                float P  = __ldcg(&Pb[(size_t)t * KM + lane]);
                int tm = t - mL - 1;
                float Pm = (tm >= 0) ? __ldcg(&Pb[(size_t)tm * KM + lane]) : 0.f;
                float Qp = (t + 1 < SS) ? __ldcg(&Qb[(size_t)(t + 1) * KM + lane]) : 0.f;
                int tp = t + mR + 1;
                float Qm = (tp < SS) ? __ldcg(&Qb[(size_t)tp * KM + lane]) : 0.f;
                float cLe = expm1f(-ph * (float)(mL + 1));
                float cRe = expm1f(-ph * (float)(mR + 1));
                float norm = fmaxf(fmaf(cLe, inv_em, cRe * inv_em) - 1.f, 1e-8f);
                float L = fmaf(-(cLe + 1.f), Pm, P);
                float R = fmaf(-(cRe + 1.f), Qm, ak * Qp);
                sm.p3.zt[s2][tl * 32 + lane] = (L + R) * (filt / norm);
            }
            __syncthreads();
            #pragma unroll
            for (int q = 0; q < 4; q++) {        // phase B: GEMV
                int tl = w * 4 + q;
                const float4* zr = (const float4*)(sm.p3.zt[s2] + tl * 32);
                float acc = 0.f;
                #pragma unroll
                for (int p = 0; p < 8; p++) {
                    float4 zv = zr[p];
                    acc = fmaf(zv.x, sm.p3.ws[(p * 4 + 0) * OC + lane], acc);
                    acc = fmaf(zv.y, sm.p3.ws[(p * 4 + 1) * OC + lane], acc);
                    acc = fmaf(zv.z, sm.p3.ws[(p * 4 + 2) * OC + lane], acc);
                    acc = fmaf(zv.w, sm.p3.ws[(p * 4 + 3) * OC + lane], acc);
                }
                sm.p3.st[s2][tl * 33 + lane] = acc;
            }
            __syncthreads();
            int o = stid >> 3, i0 = (stid & 7) * 4;
            float4 r;
            r.x = sm.p3.st[s2][(i0 + 0) * 33 + o];
            r.y = sm.p3.st[s2][(i0 + 1) * 33 + o];
            r.z = sm.p3.st[s2][(i0 + 2) * 33 + o];
            r.w = sm.p3.st[s2][(i0 + 3) * 33 + o];
            *(float4*)(out + ((size_t)(b * OC + o)) * SS + t0 + i0) = r;
            __syncthreads();
        }
    }
}

extern "C" void kernel_launch(void* const* d_in, const int* in_sizes, int n_in,
                              void* d_out, int out_size) {
    // size-based input resolution
    int ix = -1, ic = -1, idt = -1, iwla = -1, iwph = -1, ilp = -1, ipw = -1, ipb = -1;
    for (int i = 0; i < n_in; i++) {
        int s = in_sizes[i];
        if (s == SB * CH * SS)      { if (ix  < 0) ix  = i; }
        else if (s == SB)           { if (ic  < 0) ic  = i; }
        else if (s == KM * CH * OC) { if (iwla < 0) iwla = i; else if (iwph < 0) iwph = i; }
        else if (s == CH * KM)      { if (ipw < 0) ipw = i; }
        else if (s == KM)           { if (ilp < 0) ilp = i; else if (ipb < 0) ipb = i; }
        else if (s == 1)            { if (idt < 0) idt = i; }
    }
    const float* x   = (const float*)d_in[ix];
    const float* cs  = (const float*)d_in[ic];
    const float* dt  = (const float*)d_in[idt];
    const float* wla = (const float*)d_in[iwla];
    const float* wph = (const float*)d_in[iwph];
    const float* lp  = (const float*)d_in[ilp];
    const float* pw  = (const float*)d_in[ipw];
    const float* pb  = (const float*)d_in[ipb];
    float* out = (float*)d_out;

    k_fused<<<NB, 512>>>(x, wla, wph, cs, dt, lp, pw, pb, out);
}